// round 1
// baseline (speedup 1.0000x reference)
#include <cuda_runtime.h>
#include <cuda_bf16.h>

// model_6408091205990: batched tiny-GRU (N = 4096*301 independent sequences,
// T=10, I=1, H=5) + FC(5->3).  One thread per sequence, weights register-
// resident (uniform broadcast loads), full T unroll.  Compute-bound on the
// FFMA pipe; memory traffic (~64 MB) is ~8us and irrelevant.

#define NB 4096
#define NT 10
#define NS 301
#define NH 5
#define NO 3
#define NSEQ (NB * NS)
#define THREADS 128

// --- fast transcendental helpers (MUFU EX2 + RCP; rel err ~1e-6) ------------
__device__ __forceinline__ float ex2f(float x) {
    float y; asm("ex2.approx.f32 %0, %1;" : "=f"(y) : "f"(x)); return y;
}
__device__ __forceinline__ float rcpf(float x) {
    float y; asm("rcp.approx.f32 %0, %1;" : "=f"(y) : "f"(x)); return y;
}
// sigmoid(x) = 1 / (1 + 2^(-x*log2e));  saturates correctly at +-inf
__device__ __forceinline__ float sigmoid_f(float x) {
    return rcpf(1.0f + ex2f(-1.4426950408889634f * x));
}
// tanh(x) = 1 - 2/(2^(2x*log2e) + 1);   ex2 overflow -> rcp(inf)=0 -> 1  (ok)
__device__ __forceinline__ float tanh_f(float x) {
    return fmaf(-2.0f, rcpf(1.0f + ex2f(2.8853900817779268f * x)), 1.0f);
}

__global__ __launch_bounds__(THREADS)
void gru_fused_kernel(const float* __restrict__ x,
                      const float* __restrict__ w_ih,
                      const float* __restrict__ w_hh,
                      const float* __restrict__ b_ih,
                      const float* __restrict__ b_hh,
                      const float* __restrict__ fc_w,
                      const float* __restrict__ fc_b,
                      float* __restrict__ out)
{
    const int n = blockIdx.x * THREADS + threadIdx.x;
    if (n >= NSEQ) return;
    const int b = n / NS;
    const int s = n - b * NS;

    // ---- load weights (all threads hit the same addresses -> L1 broadcast) --
    float wih[3 * NH];
    float whh[3 * NH][NH];
    float brz[2 * NH];   // merged b_ih + b_hh for r and z gates
    float bin[NH];       // b_ih for n gate (kept separate: r multiplies h-part)
    float bhn[NH];       // b_hh for n gate
    #pragma unroll
    for (int g = 0; g < 3 * NH; g++) wih[g] = __ldg(&w_ih[g]);
    #pragma unroll
    for (int g = 0; g < 3 * NH; g++)
        #pragma unroll
        for (int k = 0; k < NH; k++) whh[g][k] = __ldg(&w_hh[g * NH + k]);
    #pragma unroll
    for (int g = 0; g < 2 * NH; g++) brz[g] = __ldg(&b_ih[g]) + __ldg(&b_hh[g]);
    #pragma unroll
    for (int j = 0; j < NH; j++) {
        bin[j] = __ldg(&b_ih[2 * NH + j]);
        bhn[j] = __ldg(&b_hh[2 * NH + j]);
    }

    // ---- GRU recurrence, fully unrolled -------------------------------------
    float h[NH] = {0.f, 0.f, 0.f, 0.f, 0.f};
    const float* xp = x + (size_t)b * (NT * NS) + s;

    #pragma unroll
    for (int t = 0; t < NT; t++) {
        const float xv = __ldg(xp + t * NS);
        float z[NH], nn[NH];
        #pragma unroll
        for (int j = 0; j < NH; j++) {
            float ar = fmaf(xv, wih[j],          brz[j]);
            float az = fmaf(xv, wih[NH + j],     brz[NH + j]);
            float ai = fmaf(xv, wih[2 * NH + j], bin[j]);
            float ah = bhn[j];
            #pragma unroll
            for (int k = 0; k < NH; k++) {
                ar = fmaf(whh[j][k],          h[k], ar);
                az = fmaf(whh[NH + j][k],     h[k], az);
                ah = fmaf(whh[2 * NH + j][k], h[k], ah);
            }
            const float r = sigmoid_f(ar);
            z[j]  = sigmoid_f(az);
            nn[j] = tanh_f(fmaf(r, ah, ai));
        }
        #pragma unroll
        for (int j = 0; j < NH; j++)
            h[j] = fmaf(z[j], h[j] - nn[j], nn[j]);   // (1-z)*n + z*h
    }

    // ---- FC(5 -> 3) and strided output write: out[b][o][s] ------------------
    #pragma unroll
    for (int o = 0; o < NO; o++) {
        float y = __ldg(&fc_b[o]);
        #pragma unroll
        for (int k = 0; k < NH; k++) y = fmaf(__ldg(&fc_w[o * NH + k]), h[k], y);
        out[((size_t)b * NO + o) * NS + s] = y;
    }
}

extern "C" void kernel_launch(void* const* d_in, const int* in_sizes, int n_in,
                              void* d_out, int out_size)
{
    const float* x    = (const float*)d_in[0];
    const float* w_ih = (const float*)d_in[1];
    const float* w_hh = (const float*)d_in[2];
    const float* b_ih = (const float*)d_in[3];
    const float* b_hh = (const float*)d_in[4];
    const float* fc_w = (const float*)d_in[5];
    const float* fc_b = (const float*)d_in[6];
    float* out = (float*)d_out;

    const int grid = (NSEQ + THREADS - 1) / THREADS;
    gru_fused_kernel<<<grid, THREADS>>>(x, w_ih, w_hh, b_ih, b_hh, fc_w, fc_b, out);
}

// round 2
// speedup vs baseline: 1.9850x; 1.9850x over previous
#include <cuda_runtime.h>
#include <cuda_bf16.h>

// model_6408091205990: 1.23M independent tiny GRUs (T=10, I=1, H=5) + FC(5->3).
// One thread per sequence, weights register-resident.
// Round-2: fma.rn.f32x2 packed matvecs (r/z gates paired per-j, n-gate h-dots
// paired across j) + MUFU.TANH transcendentals (sigmoid via tanh identity with
// the 0.5 pre-scale folded into the r/z weights at load time).

#define NB 4096
#define NT 10
#define NS 301
#define NH 5
#define NO 3
#define NSEQ (NB * NS)
#define THREADS 128

typedef unsigned long long ull;

__device__ __forceinline__ ull pack2(float lo, float hi) {
    ull r; asm("mov.b64 %0, {%1, %2};" : "=l"(r) : "f"(lo), "f"(hi)); return r;
}
__device__ __forceinline__ void unpack2(ull v, float& lo, float& hi) {
    asm("mov.b64 {%0, %1}, %2;" : "=f"(lo), "=f"(hi) : "l"(v));
}
__device__ __forceinline__ ull fma2(ull a, ull b, ull c) {
    ull d; asm("fma.rn.f32x2 %0, %1, %2, %3;" : "=l"(d) : "l"(a), "l"(b), "l"(c));
    return d;
}
// MUFU.TANH: single-MUFU tanh (sm_75+), rel err ~2^-11
__device__ __forceinline__ float tanh_mufu(float x) {
    float y; asm("tanh.approx.f32 %0, %1;" : "=f"(y) : "f"(x)); return y;
}

__global__ __launch_bounds__(THREADS)
void gru_fused_kernel(const float* __restrict__ x,
                      const float* __restrict__ w_ih,
                      const float* __restrict__ w_hh,
                      const float* __restrict__ b_ih,
                      const float* __restrict__ b_hh,
                      const float* __restrict__ fc_w,
                      const float* __restrict__ fc_b,
                      float* __restrict__ out)
{
    const int n = blockIdx.x * THREADS + threadIdx.x;
    if (n >= NSEQ) return;
    const int b = n / NS;
    const int s = n - b * NS;

    // ---- weight prep (uniform broadcast loads; 0.5 folded into r/z rows) ----
    // r/z gates packed as (r, z) pairs per output j.
    ull wrz_x[NH];        // (0.5*w_ih[r][j], 0.5*w_ih[z][j])
    ull brz2[NH];         // 0.5*(b_ih+b_hh) for (r, z)
    ull wrz_h[NH][NH];    // [j][k] = (0.5*w_hh[r,j,k], 0.5*w_hh[z,j,k])
    // n-gate h-dots packed across j: pairs (0,1), (2,3); j=4 scalar.
    ull wn_h2[2][NH];     // [p][k] = (w_hh[n,2p,k], w_hh[n,2p+1,k])
    float wn_h4[NH];      // w_hh[n,4,k]
    ull bn2[2];           // (b_hh[n,0],b_hh[n,1]), (b_hh[n,2],b_hh[n,3])
    float bn4;            // b_hh[n,4]
    float win_n[NH], bin_n[NH];   // x-projection of n gate (b_ih part)

    #pragma unroll
    for (int j = 0; j < NH; j++) {
        wrz_x[j] = pack2(0.5f * __ldg(&w_ih[j]), 0.5f * __ldg(&w_ih[NH + j]));
        brz2[j]  = pack2(0.5f * (__ldg(&b_ih[j]) + __ldg(&b_hh[j])),
                         0.5f * (__ldg(&b_ih[NH + j]) + __ldg(&b_hh[NH + j])));
        #pragma unroll
        for (int k = 0; k < NH; k++)
            wrz_h[j][k] = pack2(0.5f * __ldg(&w_hh[j * NH + k]),
                                0.5f * __ldg(&w_hh[(NH + j) * NH + k]));
        win_n[j] = __ldg(&w_ih[2 * NH + j]);
        bin_n[j] = __ldg(&b_ih[2 * NH + j]);
    }
    #pragma unroll
    for (int p = 0; p < 2; p++) {
        bn2[p] = pack2(__ldg(&b_hh[2 * NH + 2 * p]), __ldg(&b_hh[2 * NH + 2 * p + 1]));
        #pragma unroll
        for (int k = 0; k < NH; k++)
            wn_h2[p][k] = pack2(__ldg(&w_hh[(2 * NH + 2 * p) * NH + k]),
                                __ldg(&w_hh[(2 * NH + 2 * p + 1) * NH + k]));
    }
    bn4 = __ldg(&b_hh[2 * NH + 4]);
    #pragma unroll
    for (int k = 0; k < NH; k++) wn_h4[k] = __ldg(&w_hh[(2 * NH + 4) * NH + k]);

    // ---- GRU recurrence, fully unrolled -------------------------------------
    float h[NH] = {0.f, 0.f, 0.f, 0.f, 0.f};
    const float* xp = x + (size_t)b * (NT * NS) + s;

    #pragma unroll
    for (int t = 0; t < NT; t++) {
        const float xv = __ldg(xp + t * NS);
        const ull xv2 = pack2(xv, xv);

        ull h2[NH];
        #pragma unroll
        for (int k = 0; k < NH; k++) h2[k] = pack2(h[k], h[k]);

        // r/z pre-activations (already scaled by 0.5): 6 fma2 per j
        ull arz[NH];
        #pragma unroll
        for (int j = 0; j < NH; j++) arz[j] = fma2(xv2, wrz_x[j], brz2[j]);
        #pragma unroll
        for (int k = 0; k < NH; k++)
            #pragma unroll
            for (int j = 0; j < NH; j++)
                arz[j] = fma2(wrz_h[j][k], h2[k], arz[j]);

        // n-gate hidden dots: 2 packed pairs + 1 scalar row
        ull an2[2] = {bn2[0], bn2[1]};
        float ah4 = bn4;
        #pragma unroll
        for (int k = 0; k < NH; k++) {
            an2[0] = fma2(wn_h2[0][k], h2[k], an2[0]);
            an2[1] = fma2(wn_h2[1][k], h2[k], an2[1]);
            ah4 = fmaf(wn_h4[k], h[k], ah4);
        }
        float ah[NH];
        unpack2(an2[0], ah[0], ah[1]);
        unpack2(an2[1], ah[2], ah[3]);
        ah[4] = ah4;

        // n-gate input part
        float ai[NH];
        #pragma unroll
        for (int j = 0; j < NH; j++) ai[j] = fmaf(xv, win_n[j], bin_n[j]);

        // gate epilogue: sigmoid(x) = 0.5*tanh(0.5x)+0.5 (0.5x already in arz)
        #pragma unroll
        for (int j = 0; j < NH; j++) {
            float ar, az;
            unpack2(arz[j], ar, az);
            const float r = fmaf(0.5f, tanh_mufu(ar), 0.5f);
            const float z = fmaf(0.5f, tanh_mufu(az), 0.5f);
            const float nn = tanh_mufu(fmaf(r, ah[j], ai[j]));
            h[j] = fmaf(z, h[j] - nn, nn);   // (1-z)*n + z*h
        }
    }

    // ---- FC(5 -> 3), strided write out[b][o][s] -----------------------------
    #pragma unroll
    for (int o = 0; o < NO; o++) {
        float y = __ldg(&fc_b[o]);
        #pragma unroll
        for (int k = 0; k < NH; k++) y = fmaf(__ldg(&fc_w[o * NH + k]), h[k], y);
        out[((size_t)b * NO + o) * NS + s] = y;
    }
}

extern "C" void kernel_launch(void* const* d_in, const int* in_sizes, int n_in,
                              void* d_out, int out_size)
{
    const float* x    = (const float*)d_in[0];
    const float* w_ih = (const float*)d_in[1];
    const float* w_hh = (const float*)d_in[2];
    const float* b_ih = (const float*)d_in[3];
    const float* b_hh = (const float*)d_in[4];
    const float* fc_w = (const float*)d_in[5];
    const float* fc_b = (const float*)d_in[6];
    float* out = (float*)d_out;

    const int grid = (NSEQ + THREADS - 1) / THREADS;
    gru_fused_kernel<<<grid, THREADS>>>(x, w_ih, w_hh, b_ih, b_hh, fc_w, fc_b, out);
}

// round 3
// speedup vs baseline: 2.1267x; 1.0714x over previous
#include <cuda_runtime.h>
#include <cuda_bf16.h>

// model_6408091205990: 1.23M independent tiny GRUs (T=10, I=1, H=5) + FC(5->3).
// One thread per sequence, weights register/L1-resident.
// Round-3: t=0 h-matvec elided (h==0), epilogue packed into fma.rn.f32x2
// (r/z sigmoid pairs, h-update j-pairs), ai x-projection packed.
// fma floor ~44us, MUFU(tanh) floor ~43us -> both pipes near-balanced.

#define NB 4096
#define NT 10
#define NS 301
#define NH 5
#define NO 3
#define NSEQ (NB * NS)
#define THREADS 128

typedef unsigned long long ull;

__device__ __forceinline__ ull pack2(float lo, float hi) {
    ull r; asm("mov.b64 %0, {%1, %2};" : "=l"(r) : "f"(lo), "f"(hi)); return r;
}
__device__ __forceinline__ void unpack2(ull v, float& lo, float& hi) {
    asm("mov.b64 {%0, %1}, %2;" : "=f"(lo), "=f"(hi) : "l"(v));
}
__device__ __forceinline__ ull fma2(ull a, ull b, ull c) {
    ull d; asm("fma.rn.f32x2 %0, %1, %2, %3;" : "=l"(d) : "l"(a), "l"(b), "l"(c));
    return d;
}
// MUFU.TANH: single-MUFU tanh (sm_75+), rel err ~2^-11
__device__ __forceinline__ float tanh_mufu(float x) {
    float y; asm("tanh.approx.f32 %0, %1;" : "=f"(y) : "f"(x)); return y;
}

__global__ __launch_bounds__(THREADS)
void gru_fused_kernel(const float* __restrict__ x,
                      const float* __restrict__ w_ih,
                      const float* __restrict__ w_hh,
                      const float* __restrict__ b_ih,
                      const float* __restrict__ b_hh,
                      const float* __restrict__ fc_w,
                      const float* __restrict__ fc_b,
                      float* __restrict__ out)
{
    const int n = blockIdx.x * THREADS + threadIdx.x;
    if (n >= NSEQ) return;
    const int b = n / NS;
    const int s = n - b * NS;

    // ---- weight prep (uniform broadcast loads; 0.5 folded into r/z rows) ----
    ull wrz_x[NH];        // (0.5*w_ih[r][j], 0.5*w_ih[z][j])
    ull brz2[NH];         // 0.5*(b_ih+b_hh) for (r, z)
    ull wrz_h[NH][NH];    // [j][k] = (0.5*w_hh[r,j,k], 0.5*w_hh[z,j,k])
    ull wn_h2[2][NH];     // [p][k] = (w_hh[n,2p,k], w_hh[n,2p+1,k])
    float wn_h4[NH];      // w_hh[n,4,k]
    ull bn2[2];           // packed b_hh for n rows (0,1),(2,3)
    float bn4;            // b_hh[n,4]
    ull win2[2], bin2[2]; // packed x-proj of n gate, rows (0,1),(2,3)
    float win4, bin4;

    #pragma unroll
    for (int j = 0; j < NH; j++) {
        wrz_x[j] = pack2(0.5f * __ldg(&w_ih[j]), 0.5f * __ldg(&w_ih[NH + j]));
        brz2[j]  = pack2(0.5f * (__ldg(&b_ih[j]) + __ldg(&b_hh[j])),
                         0.5f * (__ldg(&b_ih[NH + j]) + __ldg(&b_hh[NH + j])));
        #pragma unroll
        for (int k = 0; k < NH; k++)
            wrz_h[j][k] = pack2(0.5f * __ldg(&w_hh[j * NH + k]),
                                0.5f * __ldg(&w_hh[(NH + j) * NH + k]));
    }
    #pragma unroll
    for (int p = 0; p < 2; p++) {
        bn2[p]  = pack2(__ldg(&b_hh[2 * NH + 2 * p]), __ldg(&b_hh[2 * NH + 2 * p + 1]));
        win2[p] = pack2(__ldg(&w_ih[2 * NH + 2 * p]), __ldg(&w_ih[2 * NH + 2 * p + 1]));
        bin2[p] = pack2(__ldg(&b_ih[2 * NH + 2 * p]), __ldg(&b_ih[2 * NH + 2 * p + 1]));
        #pragma unroll
        for (int k = 0; k < NH; k++)
            wn_h2[p][k] = pack2(__ldg(&w_hh[(2 * NH + 2 * p) * NH + k]),
                                __ldg(&w_hh[(2 * NH + 2 * p + 1) * NH + k]));
    }
    bn4  = __ldg(&b_hh[2 * NH + 4]);
    win4 = __ldg(&w_ih[2 * NH + 4]);
    bin4 = __ldg(&b_ih[2 * NH + 4]);
    #pragma unroll
    for (int k = 0; k < NH; k++) wn_h4[k] = __ldg(&w_hh[(2 * NH + 4) * NH + k]);

    const ull HALF2 = pack2(0.5f, 0.5f);
    const ull NEG1_2 = pack2(-1.0f, -1.0f);

    // ---- GRU recurrence, fully unrolled -------------------------------------
    // h kept as adjacent pairs (h0,h1),(h2,h3) + scalar h4.
    float h[NH] = {0.f, 0.f, 0.f, 0.f, 0.f};
    ull h01 = pack2(0.f, 0.f), h23 = h01;
    const float* xp = x + (size_t)b * (NT * NS) + s;

    #pragma unroll
    for (int t = 0; t < NT; t++) {
        const float xv = __ldg(xp + t * NS);
        const ull xv2 = pack2(xv, xv);

        // r/z pre-activations (0.5-scaled): x part
        ull arz[NH];
        #pragma unroll
        for (int j = 0; j < NH; j++) arz[j] = fma2(xv2, wrz_x[j], brz2[j]);

        // n-gate hidden part
        ull an2[2] = {bn2[0], bn2[1]};
        float ah4 = bn4;

        if (t > 0) {  // h == 0 at t == 0: skip the entire h-matvec
            ull hb[NH];
            #pragma unroll
            for (int k = 0; k < NH; k++) hb[k] = pack2(h[k], h[k]);
            #pragma unroll
            for (int k = 0; k < NH; k++) {
                #pragma unroll
                for (int j = 0; j < NH; j++)
                    arz[j] = fma2(wrz_h[j][k], hb[k], arz[j]);
                an2[0] = fma2(wn_h2[0][k], hb[k], an2[0]);
                an2[1] = fma2(wn_h2[1][k], hb[k], an2[1]);
                ah4 = fmaf(wn_h4[k], h[k], ah4);
            }
        }
        float ah[NH];
        unpack2(an2[0], ah[0], ah[1]);
        unpack2(an2[1], ah[2], ah[3]);
        ah[4] = ah4;

        // n-gate x-projection, packed across j pairs
        float ai[NH];
        {
            ull ai01 = fma2(xv2, win2[0], bin2[0]);
            ull ai23 = fma2(xv2, win2[1], bin2[1]);
            unpack2(ai01, ai[0], ai[1]);
            unpack2(ai23, ai[2], ai[3]);
            ai[4] = fmaf(xv, win4, bin4);
        }

        // epilogue: sigmoid via 0.5*tanh(0.5x)+0.5, r/z pair-packed
        float z[NH], nn[NH];
        #pragma unroll
        for (int j = 0; j < NH; j++) {
            float ar, az;
            unpack2(arz[j], ar, az);
            ull t2 = pack2(tanh_mufu(ar), tanh_mufu(az));
            ull rz = fma2(HALF2, t2, HALF2);
            float r;
            unpack2(rz, r, z[j]);
            nn[j] = tanh_mufu(fmaf(r, ah[j], ai[j]));
        }

        // h update (1-z)*n + z*h = z*(h-n) + n, j-pair packed
        {
            ull nn01 = pack2(nn[0], nn[1]);
            ull nn23 = pack2(nn[2], nn[3]);
            ull z01  = pack2(z[0], z[1]);
            ull z23  = pack2(z[2], z[3]);
            h01 = fma2(z01, fma2(nn01, NEG1_2, h01), nn01);
            h23 = fma2(z23, fma2(nn23, NEG1_2, h23), nn23);
            h[4] = fmaf(z[4], h[4] - nn[4], nn[4]);
            unpack2(h01, h[0], h[1]);
            unpack2(h23, h[2], h[3]);
        }
    }

    // ---- FC(5 -> 3), strided write out[b][o][s] -----------------------------
    #pragma unroll
    for (int o = 0; o < NO; o++) {
        float y = __ldg(&fc_b[o]);
        #pragma unroll
        for (int k = 0; k < NH; k++) y = fmaf(__ldg(&fc_w[o * NH + k]), h[k], y);
        out[((size_t)b * NO + o) * NS + s] = y;
    }
}

extern "C" void kernel_launch(void* const* d_in, const int* in_sizes, int n_in,
                              void* d_out, int out_size)
{
    const float* x    = (const float*)d_in[0];
    const float* w_ih = (const float*)d_in[1];
    const float* w_hh = (const float*)d_in[2];
    const float* b_ih = (const float*)d_in[3];
    const float* b_hh = (const float*)d_in[4];
    const float* fc_w = (const float*)d_in[5];
    const float* fc_b = (const float*)d_in[6];
    float* out = (float*)d_out;

    const int grid = (NSEQ + THREADS - 1) / THREADS;
    gru_fused_kernel<<<grid, THREADS>>>(x, w_ih, w_hh, b_ih, b_hh, fc_w, fc_b, out);
}

// round 5
// speedup vs baseline: 2.1279x; 1.0006x over previous
#include <cuda_runtime.h>
#include <cuda_bf16.h>

// model_6408091205990: 1.23M independent tiny GRUs (T=10, I=1, H=5) + FC(5->3).
// Round-4: TWO sequences per thread, interleaved. The kernel is issue/latency
// bound (fma busy ~62%, MUFU ~74%, issue 64%): a second independent recurrence
// per thread fills the MUFU/fma dependency-stall slots. Weights (~60 regs)
// are shared between the two sequences.

#define NB 4096
#define NT 10
#define NS 301
#define NH 5
#define NO 3
#define NSEQ (NB * NS)
#define NSEQ_HALF (NSEQ / 2)
#define THREADS 128

typedef unsigned long long ull;

__device__ __forceinline__ ull pack2(float lo, float hi) {
    ull r; asm("mov.b64 %0, {%1, %2};" : "=l"(r) : "f"(lo), "f"(hi)); return r;
}
__device__ __forceinline__ void unpack2(ull v, float& lo, float& hi) {
    asm("mov.b64 {%0, %1}, %2;" : "=f"(lo), "=f"(hi) : "l"(v));
}
__device__ __forceinline__ ull fma2(ull a, ull b, ull c) {
    ull d; asm("fma.rn.f32x2 %0, %1, %2, %3;" : "=l"(d) : "l"(a), "l"(b), "l"(c));
    return d;
}
__device__ __forceinline__ float tanh_mufu(float x) {
    float y; asm("tanh.approx.f32 %0, %1;" : "=f"(y) : "f"(x)); return y;
}

struct GruW {
    ull wrz_x[NH];        // (0.5*w_ih[r][j], 0.5*w_ih[z][j])
    ull brz2[NH];         // 0.5*(b_ih+b_hh) for (r, z)
    ull wrz_h[NH][NH];    // [j][k] = (0.5*w_hh[r,j,k], 0.5*w_hh[z,j,k])
    ull wn_h2[2][NH];     // [p][k] = (w_hh[n,2p,k], w_hh[n,2p+1,k])
    float wn_h4[NH];
    ull bn2[2];
    float bn4;
    ull win2[2], bin2[2];
    float win4, bin4;
    ull HALF2, NEG1_2;
};

// One GRU step for one sequence (h: 5 scalars, updated in place).
template <bool FIRST>
__device__ __forceinline__ void gru_step(const GruW& W, float h[NH], float xv)
{
    const ull xv2 = pack2(xv, xv);

    ull arz[NH];
    #pragma unroll
    for (int j = 0; j < NH; j++) arz[j] = fma2(xv2, W.wrz_x[j], W.brz2[j]);

    ull an2[2] = {W.bn2[0], W.bn2[1]};
    float ah4 = W.bn4;

    if (!FIRST) {
        ull hb[NH];
        #pragma unroll
        for (int k = 0; k < NH; k++) hb[k] = pack2(h[k], h[k]);
        #pragma unroll
        for (int k = 0; k < NH; k++) {
            #pragma unroll
            for (int j = 0; j < NH; j++)
                arz[j] = fma2(W.wrz_h[j][k], hb[k], arz[j]);
            an2[0] = fma2(W.wn_h2[0][k], hb[k], an2[0]);
            an2[1] = fma2(W.wn_h2[1][k], hb[k], an2[1]);
            ah4 = fmaf(W.wn_h4[k], h[k], ah4);
        }
    }
    float ah[NH];
    unpack2(an2[0], ah[0], ah[1]);
    unpack2(an2[1], ah[2], ah[3]);
    ah[4] = ah4;

    float ai[NH];
    {
        ull ai01 = fma2(xv2, W.win2[0], W.bin2[0]);
        ull ai23 = fma2(xv2, W.win2[1], W.bin2[1]);
        unpack2(ai01, ai[0], ai[1]);
        unpack2(ai23, ai[2], ai[3]);
        ai[4] = fmaf(xv, W.win4, W.bin4);
    }

    float z[NH], nn[NH];
    #pragma unroll
    for (int j = 0; j < NH; j++) {
        float ar, az;
        unpack2(arz[j], ar, az);
        ull t2 = pack2(tanh_mufu(ar), tanh_mufu(az));
        ull rz = fma2(W.HALF2, t2, W.HALF2);
        float r;
        unpack2(rz, r, z[j]);
        nn[j] = tanh_mufu(fmaf(r, ah[j], ai[j]));
    }

    {
        ull h01 = pack2(h[0], h[1]);
        ull h23 = pack2(h[2], h[3]);
        ull nn01 = pack2(nn[0], nn[1]);
        ull nn23 = pack2(nn[2], nn[3]);
        ull z01  = pack2(z[0], z[1]);
        ull z23  = pack2(z[2], z[3]);
        h01 = fma2(z01, fma2(nn01, W.NEG1_2, h01), nn01);
        h23 = fma2(z23, fma2(nn23, W.NEG1_2, h23), nn23);
        h[4] = fmaf(z[4], h[4] - nn[4], nn[4]);
        unpack2(h01, h[0], h[1]);
        unpack2(h23, h[2], h[3]);
    }
}

__global__ __launch_bounds__(THREADS, 4)
void gru_fused_kernel(const float* __restrict__ x,
                      const float* __restrict__ w_ih,
                      const float* __restrict__ w_hh,
                      const float* __restrict__ b_ih,
                      const float* __restrict__ b_hh,
                      const float* __restrict__ fc_w,
                      const float* __restrict__ fc_b,
                      float* __restrict__ out)
{
    const int i = blockIdx.x * THREADS + threadIdx.x;
    if (i >= NSEQ_HALF) return;
    // Two coalesced sequences per thread.
    const int nA = i;
    const int nB = i + NSEQ_HALF;
    const int bA = nA / NS, sA = nA - bA * NS;
    const int bB = nB / NS, sB = nB - bB * NS;

    // ---- weight prep (uniform broadcast loads; shared by both sequences) ----
    GruW W;
    #pragma unroll
    for (int j = 0; j < NH; j++) {
        W.wrz_x[j] = pack2(0.5f * __ldg(&w_ih[j]), 0.5f * __ldg(&w_ih[NH + j]));
        W.brz2[j]  = pack2(0.5f * (__ldg(&b_ih[j]) + __ldg(&b_hh[j])),
                           0.5f * (__ldg(&b_ih[NH + j]) + __ldg(&b_hh[NH + j])));
        #pragma unroll
        for (int k = 0; k < NH; k++)
            W.wrz_h[j][k] = pack2(0.5f * __ldg(&w_hh[j * NH + k]),
                                  0.5f * __ldg(&w_hh[(NH + j) * NH + k]));
    }
    #pragma unroll
    for (int p = 0; p < 2; p++) {
        W.bn2[p]  = pack2(__ldg(&b_hh[2 * NH + 2 * p]), __ldg(&b_hh[2 * NH + 2 * p + 1]));
        W.win2[p] = pack2(__ldg(&w_ih[2 * NH + 2 * p]), __ldg(&w_ih[2 * NH + 2 * p + 1]));
        W.bin2[p] = pack2(__ldg(&b_ih[2 * NH + 2 * p]), __ldg(&b_ih[2 * NH + 2 * p + 1]));
        #pragma unroll
        for (int k = 0; k < NH; k++)
            W.wn_h2[p][k] = pack2(__ldg(&w_hh[(2 * NH + 2 * p) * NH + k]),
                                  __ldg(&w_hh[(2 * NH + 2 * p + 1) * NH + k]));
    }
    W.bn4  = __ldg(&b_hh[2 * NH + 4]);
    W.win4 = __ldg(&w_ih[2 * NH + 4]);
    W.bin4 = __ldg(&b_ih[2 * NH + 4]);
    #pragma unroll
    for (int k = 0; k < NH; k++) W.wn_h4[k] = __ldg(&w_hh[(2 * NH + 4) * NH + k]);
    W.HALF2  = pack2(0.5f, 0.5f);
    W.NEG1_2 = pack2(-1.0f, -1.0f);

    // ---- two interleaved recurrences ---------------------------------------
    float hA[NH] = {0.f, 0.f, 0.f, 0.f, 0.f};
    float hB[NH] = {0.f, 0.f, 0.f, 0.f, 0.f};
    const float* xpA = x + (size_t)bA * (NT * NS) + sA;
    const float* xpB = x + (size_t)bB * (NT * NS) + sB;

    {
        const float xvA = __ldg(xpA);
        const float xvB = __ldg(xpB);
        gru_step<true>(W, hA, xvA);
        gru_step<true>(W, hB, xvB);
    }
    #pragma unroll
    for (int t = 1; t < NT; t++) {
        const float xvA = __ldg(xpA + t * NS);
        const float xvB = __ldg(xpB + t * NS);
        gru_step<false>(W, hA, xvA);
        gru_step<false>(W, hB, xvB);
    }

    // ---- FC(5 -> 3), strided writes out[b][o][s] ----------------------------
    #pragma unroll
    for (int o = 0; o < NO; o++) {
        float wc[NH];
        #pragma unroll
        for (int k = 0; k < NH; k++) wc[k] = __ldg(&fc_w[o * NH + k]);
        const float bc = __ldg(&fc_b[o]);
        float yA = bc, yB = bc;
        #pragma unroll
        for (int k = 0; k < NH; k++) {
            yA = fmaf(wc[k], hA[k], yA);
            yB = fmaf(wc[k], hB[k], yB);
        }
        out[((size_t)bA * NO + o) * NS + sA] = yA;
        out[((size_t)bB * NO + o) * NS + sB] = yB;
    }
}

extern "C" void kernel_launch(void* const* d_in, const int* in_sizes, int n_in,
                              void* d_out, int out_size)
{
    const float* x    = (const float*)d_in[0];
    const float* w_ih = (const float*)d_in[1];
    const float* w_hh = (const float*)d_in[2];
    const float* b_ih = (const float*)d_in[3];
    const float* b_hh = (const float*)d_in[4];
    const float* fc_w = (const float*)d_in[5];
    const float* fc_b = (const float*)d_in[6];
    float* out = (float*)d_out;

    const int grid = (NSEQ_HALF + THREADS - 1) / THREADS;
    gru_fused_kernel<<<grid, THREADS>>>(x, w_ih, w_hh, b_ih, b_hh, fc_w, fc_b, out);
}